// round 9
// baseline (speedup 1.0000x reference)
#include <cuda_runtime.h>
#include <cuda_fp16.h>
#include <cuda_bf16.h>
#include <stdint.h>

// ============================================================================
// AWQ 4-bit linear: out[128,8192] = x[128,8192] @ dequant(W)^T + bias
//
// Harness dtype set is {float32, int32, bfloat16} (per stub) — the reference's
// fp16 arrays are promoted (most likely to float32; fp32-read-as-fp16 explains
// the rel_err=inf of rounds 2-4). We detect the actual storage dtype of the
// fp16-origin inputs at runtime from the scales buffer's value range, convert
// x/scales to fp16 scratch, then run the audited mma.sync.m16n8k16 GEMM.
//
// CTA: 256 threads (8 warps, 2(M) x 4(N)), N_TILE=64 -> 128 CTAs.
// K chunk = 128 = one quant group. Double-buffered padded SMEM (272B rows).
// ============================================================================

#define N_TILE    64
#define K_DIM     8192
#define QW_COLS   1024
#define NCHUNK    64
#define ROW_BYTES 272            // 256B data + 16B pad (conflict-free)

#define A_STAGE   (128 * ROW_BYTES)   // 34816
#define B_STAGE   (64 * ROW_BYTES)    // 17408
#define SMEM_A0   0
#define SMEM_A1   A_STAGE
#define SMEM_B0   (2 * A_STAGE)
#define SMEM_B1   (2 * A_STAGE + B_STAGE)
#define SMEM_TOTAL (2 * A_STAGE + 2 * B_STAGE)   // 104448 bytes

#define X_ELEMS      1048576
#define SCALE_ELEMS  524288

// fp16 scratch (device globals are the sanctioned scratch mechanism)
__device__ __half g_x[X_ELEMS];
__device__ __half g_scales[SCALE_ELEMS];
__device__ int    g_dtype;   // 0 = fp32 storage, 1 = fp16 storage, 2 = bf16 storage

// ---------------------------------------------------------------------------
// dtype detection from scales (values in (0.001, 0.02)):
//   fp32 words:  exponent byte (w>>23)&0xFF in [117,121] for ~all words;
//                low 16 bits random.
//   fp16 pairs:  high-half fp16 exponent maps to byte 40..87 -> not f32-like.
//   bf16 pairs:  high half bf16 => (w>>23)&0xFF in [117,121] AND low half
//                bf16 => (w>>7)&0xFF also in [117,121].
// ---------------------------------------------------------------------------
__global__ void detect_dtype_kernel(const uint32_t* __restrict__ scales_raw) {
    const int lane = threadIdx.x;
    int cntHi = 0, cntLo = 0;
#pragma unroll
    for (int i = 0; i < 8; i++) {
        const uint32_t w = scales_raw[lane * 8 + i];
        const uint32_t eHi = (w >> 23) & 0xFF;
        const uint32_t eLo = (w >> 7) & 0xFF;
        cntHi += (eHi >= 110 && eHi <= 126);
        cntLo += (eLo >= 110 && eLo <= 126);
    }
#pragma unroll
    for (int off = 16; off > 0; off >>= 1) {
        cntHi += __shfl_xor_sync(0xFFFFFFFF, cntHi, off);
        cntLo += __shfl_xor_sync(0xFFFFFFFF, cntLo, off);
    }
    if (lane == 0) {
        int dt;
        if (cntHi > 192) dt = (cntLo > 192) ? 2 : 0;
        else             dt = 1;
        g_dtype = dt;
    }
}

// Convert a buffer of unknown storage (fp32/fp16/bf16) to fp16 scratch.
__global__ void convert_kernel(const void* __restrict__ src, __half* __restrict__ dst, int n) {
    const int dt = g_dtype;
    const int stride = gridDim.x * blockDim.x;
    int i = blockIdx.x * blockDim.x + threadIdx.x;
    if (dt == 0) {
        const float4* s4 = (const float4*)src;
        for (; i < n / 4; i += stride) {
            const float4 v = s4[i];
            __half2 lo = __floats2half2_rn(v.x, v.y);
            __half2 hi = __floats2half2_rn(v.z, v.w);
            uint2 o;
            o.x = *reinterpret_cast<uint32_t*>(&lo);
            o.y = *reinterpret_cast<uint32_t*>(&hi);
            *reinterpret_cast<uint2*>(dst + i * 4) = o;
        }
    } else if (dt == 2) {
        const __nv_bfloat162* s2 = (const __nv_bfloat162*)src;
        for (; i < n / 4; i += stride) {
            const __nv_bfloat162 a = s2[i * 2], b = s2[i * 2 + 1];
            __half2 lo = __floats2half2_rn(__bfloat162float(a.x), __bfloat162float(a.y));
            __half2 hi = __floats2half2_rn(__bfloat162float(b.x), __bfloat162float(b.y));
            uint2 o;
            o.x = *reinterpret_cast<uint32_t*>(&lo);
            o.y = *reinterpret_cast<uint32_t*>(&hi);
            *reinterpret_cast<uint2*>(dst + i * 4) = o;
        }
    } else {
        const uint2* s2 = (const uint2*)src;
        for (; i < n / 4; i += stride)
            *reinterpret_cast<uint2*>(dst + i * 4) = s2[i];
    }
}

// ---------------------------------------------------------------------------
// GEMM (audited; unchanged from round 4)
// ---------------------------------------------------------------------------
static __device__ __forceinline__ uint32_t smem_u32(const void* p) {
    uint32_t r;
    asm("{ .reg .u64 t; cvta.to.shared.u64 t, %1; cvt.u32.u64 %0, t; }" : "=r"(r) : "l"(p));
    return r;
}
static __device__ __forceinline__ uint32_t h2u(__half2 h) {
    return *reinterpret_cast<uint32_t*>(&h);
}

static __device__ __forceinline__ void cp_async16(uint32_t dst, const void* src) {
    asm volatile("cp.async.cg.shared.global [%0], [%1], 16;" :: "r"(dst), "l"(src) : "memory");
}
static __device__ __forceinline__ void cp_commit() {
    asm volatile("cp.async.commit_group;" ::: "memory");
}
template <int N>
static __device__ __forceinline__ void cp_wait() {
    asm volatile("cp.async.wait_group %0;" :: "n"(N) : "memory");
}

static __device__ __forceinline__ void ldsm_x4(uint32_t* r, uint32_t addr) {
    asm volatile("ldmatrix.sync.aligned.m8n8.x4.shared.b16 {%0,%1,%2,%3}, [%4];"
                 : "=r"(r[0]), "=r"(r[1]), "=r"(r[2]), "=r"(r[3]) : "r"(addr));
}
static __device__ __forceinline__ void ldsm_x2(uint32_t* r, uint32_t addr) {
    asm volatile("ldmatrix.sync.aligned.m8n8.x2.shared.b16 {%0,%1}, [%2];"
                 : "=r"(r[0]), "=r"(r[1]) : "r"(addr));
}
static __device__ __forceinline__ void mma16816(float* d, const uint32_t* a, const uint32_t* b) {
    asm volatile("mma.sync.aligned.m16n8k16.row.col.f32.f16.f16.f32 "
                 "{%0,%1,%2,%3}, {%4,%5,%6,%7}, {%8,%9}, {%0,%1,%2,%3};"
                 : "+f"(d[0]), "+f"(d[1]), "+f"(d[2]), "+f"(d[3])
                 : "r"(a[0]), "r"(a[1]), "r"(a[2]), "r"(a[3]), "r"(b[0]), "r"(b[1]));
}

// Dequant one packed int32 (8 nibbles n0..n7) -> 8 fp16 in LOGICAL order.
static __device__ __forceinline__ void dq_sts(uint32_t q, __half2 zp, __half2 s, uint32_t addr) {
    uint32_t h0, h1, h2, h3;
    asm("lop3.b32 %0, %1, 0x000F000F, 0x64006400, 0xEA;" : "=r"(h0) : "r"(q));        // (n0,n4)
    asm("lop3.b32 %0, %1, 0x000F000F, 0x64006400, 0xEA;" : "=r"(h1) : "r"(q >> 4));   // (n1,n5)
    asm("lop3.b32 %0, %1, 0x000F000F, 0x64006400, 0xEA;" : "=r"(h2) : "r"(q >> 8));   // (n2,n6)
    asm("lop3.b32 %0, %1, 0x000F000F, 0x64006400, 0xEA;" : "=r"(h3) : "r"(q >> 12));  // (n3,n7)
    uint32_t w0 = h2u(__hmul2(__hsub2(*reinterpret_cast<__half2*>(&h0), zp), s));
    uint32_t w1 = h2u(__hmul2(__hsub2(*reinterpret_cast<__half2*>(&h1), zp), s));
    uint32_t w2 = h2u(__hmul2(__hsub2(*reinterpret_cast<__half2*>(&h2), zp), s));
    uint32_t w3 = h2u(__hmul2(__hsub2(*reinterpret_cast<__half2*>(&h3), zp), s));
    uint32_t l0 = __byte_perm(w0, w1, 0x5410);  // (n0,n1)
    uint32_t l1 = __byte_perm(w2, w3, 0x5410);  // (n2,n3)
    uint32_t l2 = __byte_perm(w0, w1, 0x7632);  // (n4,n5)
    uint32_t l3 = __byte_perm(w2, w3, 0x7632);  // (n6,n7)
    asm volatile("st.shared.v4.b32 [%0], {%1,%2,%3,%4};"
                 :: "r"(addr), "r"(l0), "r"(l1), "r"(l2), "r"(l3) : "memory");
}

struct BRegs {
    uint32_t w[4];
    __half sA, sB;
    int zwA, zwB;
};

extern __shared__ char dyn_smem[];

__global__ void __launch_bounds__(256, 1)
awq_kernel(const int* __restrict__ qweight, const int* __restrict__ qzeros,
           const float* __restrict__ bias, float* __restrict__ out)
{
    const __half* x = g_x;
    const __half* scales = g_scales;
    const uint32_t sb = smem_u32(dyn_smem);
    const int tid = threadIdx.x;
    const int wid = tid >> 5;
    const int lid = tid & 31;
    const int n0 = blockIdx.x * N_TILE;

    // ---- A fill mapping: 2048 16B-slots over 256 threads x 8 iters ----
    uint32_t a_dst_off[8], a_src_off[8];
#pragma unroll
    for (int it = 0; it < 8; it++) {
        const int j = tid + 256 * it;
        const int row = j >> 4, u = j & 15;
        a_dst_off[it] = (uint32_t)(row * ROW_BYTES + u * 16);
        a_src_off[it] = (uint32_t)(row * K_DIM + u * 8);
    }
    // ---- B fill mapping ----
    const int bl = tid & 7, bg = tid >> 3;
    const uint32_t b_off0 = (uint32_t)(bg * ROW_BYTES + bl * 16);
    const uint32_t b_off1 = (uint32_t)((bg + 32) * ROW_BYTES + bl * 16);
    const int* qb0 = qweight + (n0 + bg) * QW_COLS + bl;
    const __half* sRowA = scales + (n0 + bg) * 64;
    const __half* sRowB = scales + (n0 + bg + 32) * 64;
    const int* zRowA = qzeros + (n0 + bg) * 8;
    const int* zRowB = qzeros + (n0 + bg + 32) * 8;

    // ---- ldmatrix addressing ----
    const int warp_m = wid >> 2;
    const int warp_n = wid & 3;
    const int lrowA = lid & 15;
    const int kblkA = (lid >> 4) & 1;
    uint32_t rowA_off[4];
#pragma unroll
    for (int mt = 0; mt < 4; mt++)
        rowA_off[mt] = (uint32_t)((warp_m * 64 + mt * 16 + lrowA) * ROW_BYTES + kblkA * 16);
    const int lB = lid & 15;
    const int kblkB = lB >> 3;
    uint32_t rowB_off[2];
#pragma unroll
    for (int nt = 0; nt < 2; nt++)
        rowB_off[nt] = (uint32_t)((warp_n * 16 + nt * 8 + (lB & 7)) * ROW_BYTES + kblkB * 16);

    float acc[4][2][4];
#pragma unroll
    for (int mt = 0; mt < 4; mt++)
#pragma unroll
        for (int nt = 0; nt < 2; nt++)
#pragma unroll
            for (int e = 0; e < 4; e++) acc[mt][nt][e] = 0.0f;

    auto fill_A = [&](int i, int stage) {
        const uint32_t as = sb + (stage ? SMEM_A1 : SMEM_A0);
        const __half* xp = x + i * 128;
#pragma unroll
        for (int it = 0; it < 8; it++)
            cp_async16(as + a_dst_off[it], xp + a_src_off[it]);
        cp_commit();
    };
    auto load_B = [&](int i, BRegs& r) {
        const int* qb = qb0 + i * 16;
        r.w[0] = (uint32_t)qb[0];
        r.w[1] = (uint32_t)qb[32 * QW_COLS];
        r.w[2] = (uint32_t)qb[8];
        r.w[3] = (uint32_t)qb[32 * QW_COLS + 8];
        r.sA = sRowA[i];
        r.sB = sRowB[i];
        r.zwA = zRowA[i >> 3];
        r.zwB = zRowB[i >> 3];
    };
    auto store_B = [&](int i, int stage, const BRegs& r) {
        const uint32_t bb = sb + (stage ? SMEM_B1 : SMEM_B0);
        const int zA = (r.zwA >> ((i & 7) * 4)) & 15;
        const int zB = (r.zwB >> ((i & 7) * 4)) & 15;
        const __half2 zpA = __float2half2_rn(1024.0f + (float)zA);
        const __half2 zpB = __float2half2_rn(1024.0f + (float)zB);
        const __half2 s2A = __half2half2(r.sA);
        const __half2 s2B = __half2half2(r.sB);
        dq_sts(r.w[0], zpA, s2A, bb + b_off0);
        dq_sts(r.w[1], zpB, s2B, bb + b_off1);
        dq_sts(r.w[2], zpA, s2A, bb + b_off0 + 128);
        dq_sts(r.w[3], zpB, s2B, bb + b_off1 + 128);
    };
    auto compute = [&](int stage) {
        const uint32_t ab = sb + (stage ? SMEM_A1 : SMEM_A0);
        const uint32_t bb = sb + (stage ? SMEM_B1 : SMEM_B0);
#pragma unroll
        for (int w = 0; w < 8; w++) {
            uint32_t bf[2][2];
            ldsm_x2(bf[0], bb + rowB_off[0] + 32 * w);
            ldsm_x2(bf[1], bb + rowB_off[1] + 32 * w);
#pragma unroll
            for (int mt = 0; mt < 4; mt++) {
                uint32_t af[4];
                ldsm_x4(af, ab + rowA_off[mt] + 32 * w);
                mma16816(acc[mt][0], af, bf[0]);
                mma16816(acc[mt][1], af, bf[1]);
            }
        }
    };

    // ---- prologue ----
    fill_A(0, 0);
    fill_A(1, 1);
    BRegs rb, rbn;
    load_B(0, rb);
    load_B(1, rbn);
    store_B(0, 0, rb);
    store_B(1, 1, rbn);

    // ---- mainloop ----
#pragma unroll 1
    for (int i = 0; i < NCHUNK; i++) {
        const int s = i & 1;
        if (i + 1 < NCHUNK) cp_wait<1>(); else cp_wait<0>();
        __syncthreads();
        if (i + 2 < NCHUNK) load_B(i + 2, rbn);
        compute(s);
        __syncthreads();
        if (i + 2 < NCHUNK) {
            fill_A(i + 2, s);
            store_B(i + 2, s, rbn);
        }
    }

    // ---- epilogue: fp16 round (match fp16 einsum), + fp32 bias ----
    const int r0 = lid >> 2;
    const int c0 = (lid & 3) * 2;
#pragma unroll
    for (int mt = 0; mt < 4; mt++) {
#pragma unroll
        for (int nt = 0; nt < 2; nt++) {
            const int n = n0 + warp_n * 16 + nt * 8 + c0;
            const float bx = bias[n], by = bias[n + 1];
            const int m = warp_m * 64 + mt * 16 + r0;
            float2 o0, o1;
            o0.x = __half2float(__float2half_rn(acc[mt][nt][0])) + bx;
            o0.y = __half2float(__float2half_rn(acc[mt][nt][1])) + by;
            o1.x = __half2float(__float2half_rn(acc[mt][nt][2])) + bx;
            o1.y = __half2float(__float2half_rn(acc[mt][nt][3])) + by;
            *reinterpret_cast<float2*>(out + (size_t)m * 8192 + n) = o0;
            *reinterpret_cast<float2*>(out + (size_t)(m + 8) * 8192 + n) = o1;
        }
    }
}

// ===========================================================================
// Host: bind inputs BY ELEMENT COUNT (all distinct) — immune to ordering.
//   x 1048576 | qweight 8388608 | scales 524288 | qzeros 65536 | bias 8192
// ===========================================================================
extern "C" void kernel_launch(void* const* d_in, const int* in_sizes, int n_in,
                              void* d_out, int out_size) {
    const void* x_raw = nullptr;
    const int* qweight = nullptr;
    const void* scales_raw = nullptr;
    const int* qzeros = nullptr;
    const float* bias = nullptr;

    for (int i = 0; i < n_in; i++) {
        switch (in_sizes[i]) {
            case X_ELEMS:     x_raw      = d_in[i];              break;
            case 8388608:     qweight    = (const int*)d_in[i];  break;
            case SCALE_ELEMS: scales_raw = d_in[i];              break;
            case 65536:       qzeros     = (const int*)d_in[i];  break;
            case 8192:        bias       = (const float*)d_in[i]; break;
            default: break;
        }
    }

    float* out = (float*)d_out;

    __half* gx = nullptr;
    __half* gs = nullptr;
    cudaGetSymbolAddress((void**)&gx, g_x);
    cudaGetSymbolAddress((void**)&gs, g_scales);

    detect_dtype_kernel<<<1, 32>>>((const uint32_t*)scales_raw);
    convert_kernel<<<256, 256>>>(x_raw, gx, X_ELEMS);
    convert_kernel<<<256, 256>>>(scales_raw, gs, SCALE_ELEMS);

    cudaFuncSetAttribute(awq_kernel, cudaFuncAttributeMaxDynamicSharedMemorySize, SMEM_TOTAL);
    awq_kernel<<<8192 / N_TILE, 256, SMEM_TOTAL>>>(qweight, qzeros, bias, out);
}

// round 10
// speedup vs baseline: 1.0584x; 1.0584x over previous
#include <cuda_runtime.h>
#include <cuda_fp16.h>
#include <cuda_bf16.h>
#include <stdint.h>

// ============================================================================
// AWQ 4-bit linear: out[128,8192] = x[128,8192] @ dequant(W)^T + bias
// mma.sync.m16n8k16, 3-stage SMEM ring, single barrier per K-chunk so that
// dequant STS + cp.async A-fill overlap HMMA compute across warps.
// CTA: 256 threads (8 warps, 4(M) x 2(N)), N_TILE=64 -> 128 CTAs.
// K chunk = 128 = one quant group. Padded SMEM rows (272B), conflict-free.
// fp16-origin inputs (x, scales) arrive promoted (fp32/bf16/fp16-packed);
// detected from scales' exponent stats, converted once to fp16 scratch.
// ============================================================================

#define N_TILE    64
#define K_DIM     8192
#define QW_COLS   1024
#define NCHUNK    64
#define ROW_BYTES 272            // 256B data + 16B pad (conflict-free)

#define A_STAGE   (128 * ROW_BYTES)   // 34816
#define B_STAGE   (64 * ROW_BYTES)    // 17408
#define STAGE_SZ  (A_STAGE + B_STAGE) // 52224
#define NSTAGE    3
#define SMEM_TOTAL (NSTAGE * STAGE_SZ)  // 156672 bytes

#define X_ELEMS      1048576
#define SCALE_ELEMS  524288

__device__ __half g_x[X_ELEMS];
__device__ __half g_scales[SCALE_ELEMS];
__device__ int    g_dtype;   // 0 = fp32 storage, 1 = fp16 storage, 2 = bf16

// ---------------------------------------------------------------------------
// dtype detection from scales (values in (0.001, 0.02))
// ---------------------------------------------------------------------------
__global__ void detect_dtype_kernel(const uint32_t* __restrict__ scales_raw) {
    const int lane = threadIdx.x;
    int cntHi = 0, cntLo = 0;
#pragma unroll
    for (int i = 0; i < 8; i++) {
        const uint32_t w = scales_raw[lane * 8 + i];
        const uint32_t eHi = (w >> 23) & 0xFF;
        const uint32_t eLo = (w >> 7) & 0xFF;
        cntHi += (eHi >= 110 && eHi <= 126);
        cntLo += (eLo >= 110 && eLo <= 126);
    }
#pragma unroll
    for (int off = 16; off > 0; off >>= 1) {
        cntHi += __shfl_xor_sync(0xFFFFFFFF, cntHi, off);
        cntLo += __shfl_xor_sync(0xFFFFFFFF, cntLo, off);
    }
    if (lane == 0) {
        int dt;
        if (cntHi > 192) dt = (cntLo > 192) ? 2 : 0;
        else             dt = 1;
        g_dtype = dt;
    }
}

__global__ void convert_kernel(const void* __restrict__ src, __half* __restrict__ dst, int n) {
    const int dt = g_dtype;
    const int stride = gridDim.x * blockDim.x;
    int i = blockIdx.x * blockDim.x + threadIdx.x;
    if (dt == 0) {
        const float4* s4 = (const float4*)src;
        for (; i < n / 4; i += stride) {
            const float4 v = s4[i];
            __half2 lo = __floats2half2_rn(v.x, v.y);
            __half2 hi = __floats2half2_rn(v.z, v.w);
            uint2 o;
            o.x = *reinterpret_cast<uint32_t*>(&lo);
            o.y = *reinterpret_cast<uint32_t*>(&hi);
            *reinterpret_cast<uint2*>(dst + i * 4) = o;
        }
    } else if (dt == 2) {
        const __nv_bfloat162* s2 = (const __nv_bfloat162*)src;
        for (; i < n / 4; i += stride) {
            const __nv_bfloat162 a = s2[i * 2], b = s2[i * 2 + 1];
            __half2 lo = __floats2half2_rn(__bfloat162float(a.x), __bfloat162float(a.y));
            __half2 hi = __floats2half2_rn(__bfloat162float(b.x), __bfloat162float(b.y));
            uint2 o;
            o.x = *reinterpret_cast<uint32_t*>(&lo);
            o.y = *reinterpret_cast<uint32_t*>(&hi);
            *reinterpret_cast<uint2*>(dst + i * 4) = o;
        }
    } else {
        const uint2* s2 = (const uint2*)src;
        for (; i < n / 4; i += stride)
            *reinterpret_cast<uint2*>(dst + i * 4) = s2[i];
    }
}

// ---------------------------------------------------------------------------
// GEMM helpers
// ---------------------------------------------------------------------------
static __device__ __forceinline__ uint32_t smem_u32(const void* p) {
    uint32_t r;
    asm("{ .reg .u64 t; cvta.to.shared.u64 t, %1; cvt.u32.u64 %0, t; }" : "=r"(r) : "l"(p));
    return r;
}
static __device__ __forceinline__ uint32_t h2u(__half2 h) {
    return *reinterpret_cast<uint32_t*>(&h);
}
static __device__ __forceinline__ void cp_async16(uint32_t dst, const void* src) {
    asm volatile("cp.async.cg.shared.global [%0], [%1], 16;" :: "r"(dst), "l"(src) : "memory");
}
static __device__ __forceinline__ void cp_commit() {
    asm volatile("cp.async.commit_group;" ::: "memory");
}
template <int N>
static __device__ __forceinline__ void cp_wait() {
    asm volatile("cp.async.wait_group %0;" :: "n"(N) : "memory");
}
static __device__ __forceinline__ void ldsm_x4(uint32_t* r, uint32_t addr) {
    asm volatile("ldmatrix.sync.aligned.m8n8.x4.shared.b16 {%0,%1,%2,%3}, [%4];"
                 : "=r"(r[0]), "=r"(r[1]), "=r"(r[2]), "=r"(r[3]) : "r"(addr));
}
static __device__ __forceinline__ void mma16816(float* d, const uint32_t* a, const uint32_t* b) {
    asm volatile("mma.sync.aligned.m16n8k16.row.col.f32.f16.f16.f32 "
                 "{%0,%1,%2,%3}, {%4,%5,%6,%7}, {%8,%9}, {%0,%1,%2,%3};"
                 : "+f"(d[0]), "+f"(d[1]), "+f"(d[2]), "+f"(d[3])
                 : "r"(a[0]), "r"(a[1]), "r"(a[2]), "r"(a[3]), "r"(b[0]), "r"(b[1]));
}

// Dequant one packed int32 (8 nibbles n0..n7) -> 8 fp16 in LOGICAL order.
static __device__ __forceinline__ void dq_sts(uint32_t q, __half2 zp, __half2 s, uint32_t addr) {
    uint32_t h0, h1, h2, h3;
    asm("lop3.b32 %0, %1, 0x000F000F, 0x64006400, 0xEA;" : "=r"(h0) : "r"(q));        // (n0,n4)
    asm("lop3.b32 %0, %1, 0x000F000F, 0x64006400, 0xEA;" : "=r"(h1) : "r"(q >> 4));   // (n1,n5)
    asm("lop3.b32 %0, %1, 0x000F000F, 0x64006400, 0xEA;" : "=r"(h2) : "r"(q >> 8));   // (n2,n6)
    asm("lop3.b32 %0, %1, 0x000F000F, 0x64006400, 0xEA;" : "=r"(h3) : "r"(q >> 12));  // (n3,n7)
    uint32_t w0 = h2u(__hmul2(__hsub2(*reinterpret_cast<__half2*>(&h0), zp), s));
    uint32_t w1 = h2u(__hmul2(__hsub2(*reinterpret_cast<__half2*>(&h1), zp), s));
    uint32_t w2 = h2u(__hmul2(__hsub2(*reinterpret_cast<__half2*>(&h2), zp), s));
    uint32_t w3 = h2u(__hmul2(__hsub2(*reinterpret_cast<__half2*>(&h3), zp), s));
    uint32_t l0 = __byte_perm(w0, w1, 0x5410);  // (n0,n1)
    uint32_t l1 = __byte_perm(w2, w3, 0x5410);  // (n2,n3)
    uint32_t l2 = __byte_perm(w0, w1, 0x7632);  // (n4,n5)
    uint32_t l3 = __byte_perm(w2, w3, 0x7632);  // (n6,n7)
    asm volatile("st.shared.v4.b32 [%0], {%1,%2,%3,%4};"
                 :: "r"(addr), "r"(l0), "r"(l1), "r"(l2), "r"(l3) : "memory");
}

struct BRegs {
    uint32_t w[4];
    __half sA, sB;
    int zwA, zwB;
};

extern __shared__ char dyn_smem[];

__global__ void __launch_bounds__(256, 1)
awq_kernel(const int* __restrict__ qweight, const int* __restrict__ qzeros,
           const float* __restrict__ bias, float* __restrict__ out)
{
    const __half* x = g_x;
    const __half* scales = g_scales;
    const uint32_t sb = smem_u32(dyn_smem);
    const int tid = threadIdx.x;
    const int wid = tid >> 5;
    const int lid = tid & 31;
    const int n0 = blockIdx.x * N_TILE;

    // ---- A fill mapping: 2048 16B-slots over 256 threads x 8 iters ----
    uint32_t a_dst_off[8], a_src_off[8];
#pragma unroll
    for (int it = 0; it < 8; it++) {
        const int j = tid + 256 * it;
        const int row = j >> 4, u = j & 15;
        a_dst_off[it] = (uint32_t)(row * ROW_BYTES + u * 16);
        a_src_off[it] = (uint32_t)(row * K_DIM + u * 8);
    }
    // ---- B dequant mapping: thread -> rows {bg, bg+32}, k-units {bl, bl+8} ----
    const int bl = tid & 7, bg = tid >> 3;
    const uint32_t b_off0 = (uint32_t)(bg * ROW_BYTES + bl * 16);
    const uint32_t b_off1 = (uint32_t)((bg + 32) * ROW_BYTES + bl * 16);
    const int* qb0 = qweight + (n0 + bg) * QW_COLS + bl;
    const __half* sRowA = scales + (n0 + bg) * 64;
    const __half* sRowB = scales + (n0 + bg + 32) * 64;
    const int* zRowA = qzeros + (n0 + bg) * 8;
    const int* zRowB = qzeros + (n0 + bg + 32) * 8;

    // ---- compute-side addressing: warp grid 4(M) x 2(N) ----
    const int warp_m = wid >> 1;                  // 0..3 -> rows [warp_m*32, +32)
    const int warp_n = wid & 1;                   // 0..1 -> cols [warp_n*32, +32)
    const int lrowA = lid & 15;
    const int kblkA = (lid >> 4) & 1;
    uint32_t rowA_off[2];
#pragma unroll
    for (int mt = 0; mt < 2; mt++)
        rowA_off[mt] = (uint32_t)((warp_m * 32 + mt * 16 + lrowA) * ROW_BYTES + kblkA * 16);
    // B ldsm_x4: 4 matrices (n0-7,k0-7),(n0-7,k8-15),(n8-15,k0-7),(n8-15,k8-15)
    const int gB = lid >> 3, rB = lid & 7;
    uint32_t bB_off[2];
#pragma unroll
    for (int pair = 0; pair < 2; pair++)
        bB_off[pair] = (uint32_t)((warp_n * 32 + pair * 16 + (gB >> 1) * 8 + rB) * ROW_BYTES
                                  + (gB & 1) * 16);

    float acc[2][4][4];
#pragma unroll
    for (int mt = 0; mt < 2; mt++)
#pragma unroll
        for (int nt = 0; nt < 4; nt++)
#pragma unroll
            for (int e = 0; e < 4; e++) acc[mt][nt][e] = 0.0f;

    auto fill_A = [&](int i, int stage) {
        const uint32_t as = sb + stage * STAGE_SZ;
        const __half* xp = x + i * 128;
#pragma unroll
        for (int it = 0; it < 8; it++)
            cp_async16(as + a_dst_off[it], xp + a_src_off[it]);
        cp_commit();
    };
    auto load_B = [&](int i, BRegs& r) {
        const int* qb = qb0 + i * 16;
        r.w[0] = (uint32_t)qb[0];
        r.w[1] = (uint32_t)qb[32 * QW_COLS];
        r.w[2] = (uint32_t)qb[8];
        r.w[3] = (uint32_t)qb[32 * QW_COLS + 8];
        r.sA = sRowA[i];
        r.sB = sRowB[i];
        r.zwA = zRowA[i >> 3];
        r.zwB = zRowB[i >> 3];
    };
    auto store_B = [&](int i, int stage, const BRegs& r) {
        const uint32_t bb = sb + stage * STAGE_SZ + A_STAGE;
        const int zA = (r.zwA >> ((i & 7) * 4)) & 15;
        const int zB = (r.zwB >> ((i & 7) * 4)) & 15;
        const __half2 zpA = __float2half2_rn(1024.0f + (float)zA);
        const __half2 zpB = __float2half2_rn(1024.0f + (float)zB);
        const __half2 s2A = __half2half2(r.sA);
        const __half2 s2B = __half2half2(r.sB);
        dq_sts(r.w[0], zpA, s2A, bb + b_off0);
        dq_sts(r.w[1], zpB, s2B, bb + b_off1);
        dq_sts(r.w[2], zpA, s2A, bb + b_off0 + 128);
        dq_sts(r.w[3], zpB, s2B, bb + b_off1 + 128);
    };
    auto compute = [&](int stage) {
        const uint32_t ab = sb + stage * STAGE_SZ;
        const uint32_t bb = ab + A_STAGE;
#pragma unroll
        for (int w = 0; w < 8; w++) {
            uint32_t bf[2][4];
            ldsm_x4(bf[0], bb + bB_off[0] + 32 * w);
            ldsm_x4(bf[1], bb + bB_off[1] + 32 * w);
#pragma unroll
            for (int mt = 0; mt < 2; mt++) {
                uint32_t af[4];
                ldsm_x4(af, ab + rowA_off[mt] + 32 * w);
                mma16816(acc[mt][0], af, bf[0] + 0);
                mma16816(acc[mt][1], af, bf[0] + 2);
                mma16816(acc[mt][2], af, bf[1] + 0);
                mma16816(acc[mt][3], af, bf[1] + 2);
            }
        }
    };

    // ---- prologue: chunks 0,1 into stages 0,1; regs for chunk 2 ----
    fill_A(0, 0);
    fill_A(1, 1);
    BRegs rcur, rnext;
    load_B(0, rcur);
    load_B(1, rnext);
    store_B(0, 0, rcur);
    store_B(1, 1, rnext);
    load_B(2, rcur);                 // rcur holds chunk 2 data for iter 0

    // ---- mainloop: ONE barrier per chunk; fill overlaps compute ----
#pragma unroll 1
    for (int i = 0; i < NCHUNK; i++) {
        if (i + 2 < NCHUNK) cp_wait<1>(); else cp_wait<0>();
        __syncthreads();             // A(i)+B(i) visible; stage (i+2)%3 free
        if (i + 3 < NCHUNK) load_B(i + 3, rnext);
        if (i + 2 < NCHUNK) {
            store_B(i + 2, (i + 2) % 3, rcur);
            fill_A(i + 2, (i + 2) % 3);
        }
        compute(i % 3);
        rcur = rnext;
    }

    // ---- epilogue: fp16 round (match fp16 einsum), + fp32 bias ----
    const int r0 = lid >> 2;
    const int c0 = (lid & 3) * 2;
#pragma unroll
    for (int mt = 0; mt < 2; mt++) {
#pragma unroll
        for (int nt = 0; nt < 4; nt++) {
            const int n = n0 + warp_n * 32 + nt * 8 + c0;
            const float bx = bias[n], by = bias[n + 1];
            const int m = warp_m * 32 + mt * 16 + r0;
            float2 o0, o1;
            o0.x = __half2float(__float2half_rn(acc[mt][nt][0])) + bx;
            o0.y = __half2float(__float2half_rn(acc[mt][nt][1])) + by;
            o1.x = __half2float(__float2half_rn(acc[mt][nt][2])) + bx;
            o1.y = __half2float(__float2half_rn(acc[mt][nt][3])) + by;
            *reinterpret_cast<float2*>(out + (size_t)m * 8192 + n) = o0;
            *reinterpret_cast<float2*>(out + (size_t)(m + 8) * 8192 + n) = o1;
        }
    }
}

// ===========================================================================
// Host: bind inputs BY ELEMENT COUNT (all distinct) — immune to ordering.
//   x 1048576 | qweight 8388608 | scales 524288 | qzeros 65536 | bias 8192
// ===========================================================================
extern "C" void kernel_launch(void* const* d_in, const int* in_sizes, int n_in,
                              void* d_out, int out_size) {
    const void* x_raw = nullptr;
    const int* qweight = nullptr;
    const void* scales_raw = nullptr;
    const int* qzeros = nullptr;
    const float* bias = nullptr;

    for (int i = 0; i < n_in; i++) {
        switch (in_sizes[i]) {
            case X_ELEMS:     x_raw      = d_in[i];               break;
            case 8388608:     qweight    = (const int*)d_in[i];   break;
            case SCALE_ELEMS: scales_raw = d_in[i];               break;
            case 65536:       qzeros     = (const int*)d_in[i];   break;
            case 8192:        bias       = (const float*)d_in[i]; break;
            default: break;
        }
    }

    float* out = (float*)d_out;

    __half* gx = nullptr;
    __half* gs = nullptr;
    cudaGetSymbolAddress((void**)&gx, g_x);
    cudaGetSymbolAddress((void**)&gs, g_scales);

    detect_dtype_kernel<<<1, 32>>>((const uint32_t*)scales_raw);
    convert_kernel<<<256, 256>>>(x_raw, gx, X_ELEMS);
    convert_kernel<<<64, 256>>>(scales_raw, gs, SCALE_ELEMS);

    cudaFuncSetAttribute(awq_kernel, cudaFuncAttributeMaxDynamicSharedMemorySize, SMEM_TOTAL);
    awq_kernel<<<8192 / N_TILE, 256, SMEM_TOTAL>>>(qweight, qzeros, bias, out);
}